// round 2
// baseline (speedup 1.0000x reference)
#include <cuda_runtime.h>
#include <cstdint>

// Problem constants (fixed by setup_inputs)
#define BATCH 8
#define NPTS  4096
#define MPTS  4096
#define CDIM  128

#define TILE  128
#define BK    16
#define PITCH 130   // k-major smem pitch: conflict-free transposed stores, even for float2 reads

#define INF_BITS 0x7F800000u

// Scratch (no allocation allowed) — 8*4096 entries each
__device__ unsigned g_rowmin[BATCH * NPTS];
__device__ unsigned g_colmin[BATCH * MPTS];
__device__ float    g_norm1[BATCH * NPTS];
__device__ float    g_norm2[BATCH * MPTS];

// Packed fp32x2 FMA (Blackwell): 2 FMAs per instruction, 2x FFMA throughput
__device__ __forceinline__ unsigned long long ffma2(unsigned long long a,
                                                    unsigned long long b,
                                                    unsigned long long c) {
    unsigned long long d;
    asm("fma.rn.f32x2 %0, %1, %2, %3;" : "=l"(d) : "l"(a), "l"(b), "l"(c));
    return d;
}
__device__ __forceinline__ unsigned long long pack2(float x) {
    unsigned long long r;
    asm("mov.b64 %0, {%1, %1};" : "=l"(r) : "r"(__float_as_uint(x)));
    return r;
}

// ---------------------------------------------------------------------------
// Kernel 1: per-point squared norms + init min arrays to +inf
// ---------------------------------------------------------------------------
__global__ void prep_kernel(const float* __restrict__ s1,
                            const float* __restrict__ s2) {
    int idx = blockIdx.x * blockDim.x + threadIdx.x;
    const int total1 = BATCH * NPTS;
    const int total2 = BATCH * MPTS;
    if (idx < total1) {
        const float4* p = reinterpret_cast<const float4*>(s1 + (size_t)idx * CDIM);
        float s = 0.f;
#pragma unroll
        for (int i = 0; i < CDIM / 4; i++) {
            float4 v = p[i];
            s += v.x * v.x + v.y * v.y + v.z * v.z + v.w * v.w;
        }
        g_norm1[idx] = s;
        g_rowmin[idx] = INF_BITS;
    } else if (idx < total1 + total2) {
        int j = idx - total1;
        const float4* p = reinterpret_cast<const float4*>(s2 + (size_t)j * CDIM);
        float s = 0.f;
#pragma unroll
        for (int i = 0; i < CDIM / 4; i++) {
            float4 v = p[i];
            s += v.x * v.x + v.y * v.y + v.z * v.z + v.w * v.w;
        }
        g_norm2[j] = s;
        g_colmin[j] = INF_BITS;
    }
}

// ---------------------------------------------------------------------------
// Kernel 2: tiled distance + min reduction.
// Block: 128x128 output tile, 256 threads, 8x8 register tile per thread.
// Thread (tx,ty): rows = ty + 16*i (i=0..7), cols = 2*tx + 32*j + s (j=0..3, s=0..1)
// ---------------------------------------------------------------------------
__global__ __launch_bounds__(256, 2)
void chamfer_main(const float* __restrict__ s1, const float* __restrict__ s2) {
    __shared__ float As[BK][PITCH];   // k-major: As[k][n_local]
    __shared__ float Bs[BK][PITCH];   // k-major: Bs[k][m_local]
    __shared__ unsigned rmin_s[TILE];
    __shared__ unsigned cmin_s[TILE];

    const int t  = threadIdx.x;
    const int tx = t & 15;
    const int ty = t >> 4;
    const int bcol = blockIdx.x * TILE;
    const int brow = blockIdx.y * TILE;
    const int b    = blockIdx.z;

    const float* Ag = s1 + (size_t)b * NPTS * CDIM;
    const float* Bg = s2 + (size_t)b * MPTS * CDIM;

    unsigned long long acc[8][4];
#pragma unroll
    for (int i = 0; i < 8; i++)
#pragma unroll
        for (int j = 0; j < 4; j++) acc[i][j] = 0ULL;

    const int lc4  = t & 3;    // float4-column within k-chunk
    const int lrow = t >> 2;   // row 0..63

    if (t < TILE) rmin_s[t] = INF_BITS;
    else          cmin_s[t - TILE] = INF_BITS;

    for (int kc = 0; kc < CDIM; kc += BK) {
        __syncthreads();
        // Load + transpose 128x16 chunk of A and B into k-major smem.
        // Store banks: (4*lc4+j)*130 + row  ->  8*lc4 + rowoff (+2j) mod 32: conflict-free.
#pragma unroll
        for (int h = 0; h < 2; h++) {
            int row = lrow + 64 * h;
            float4 ga = *reinterpret_cast<const float4*>(Ag + (size_t)(brow + row) * CDIM + kc + 4 * lc4);
            float4 gb = *reinterpret_cast<const float4*>(Bg + (size_t)(bcol + row) * CDIM + kc + 4 * lc4);
            As[4 * lc4 + 0][row] = ga.x;
            As[4 * lc4 + 1][row] = ga.y;
            As[4 * lc4 + 2][row] = ga.z;
            As[4 * lc4 + 3][row] = ga.w;
            Bs[4 * lc4 + 0][row] = gb.x;
            Bs[4 * lc4 + 1][row] = gb.y;
            Bs[4 * lc4 + 2][row] = gb.z;
            Bs[4 * lc4 + 3][row] = gb.w;
        }
        __syncthreads();

#pragma unroll
        for (int k = 0; k < BK; k++) {
            unsigned long long bv[4];
#pragma unroll
            for (int j = 0; j < 4; j++)
                bv[j] = *reinterpret_cast<const unsigned long long*>(&Bs[k][2 * tx + 32 * j]);
#pragma unroll
            for (int i = 0; i < 8; i++) {
                unsigned long long av = pack2(As[k][ty + 16 * i]);
#pragma unroll
                for (int j = 0; j < 4; j++)
                    acc[i][j] = ffma2(av, bv[j], acc[i][j]);
            }
        }
    }

    // ---- Epilogue: d = sqrt(max(n1 + n2 - 2*dot, 0)), fold mins ----
    const float INF = __uint_as_float(INF_BITS);
    float n1v[8], n2v[8];
#pragma unroll
    for (int i = 0; i < 8; i++)
        n1v[i] = g_norm1[b * NPTS + brow + ty + 16 * i];
#pragma unroll
    for (int j = 0; j < 4; j++) {
        n2v[2 * j]     = g_norm2[b * MPTS + bcol + 2 * tx + 32 * j];
        n2v[2 * j + 1] = g_norm2[b * MPTS + bcol + 2 * tx + 32 * j + 1];
    }

    float cminv[8];
#pragma unroll
    for (int j = 0; j < 8; j++) cminv[j] = INF;

#pragma unroll
    for (int i = 0; i < 8; i++) {
        float rmv = INF;
#pragma unroll
        for (int j = 0; j < 4; j++) {
            float dotx = __uint_as_float((unsigned)(acc[i][j] & 0xFFFFFFFFull));
            float doty = __uint_as_float((unsigned)(acc[i][j] >> 32));
            float dx = sqrtf(fmaxf(n1v[i] + n2v[2 * j]     - 2.0f * dotx, 0.0f));
            float dy = sqrtf(fmaxf(n1v[i] + n2v[2 * j + 1] - 2.0f * doty, 0.0f));
            rmv = fminf(rmv, fminf(dx, dy));
            cminv[2 * j]     = fminf(cminv[2 * j], dx);
            cminv[2 * j + 1] = fminf(cminv[2 * j + 1], dy);
        }
        atomicMin(&rmin_s[ty + 16 * i], __float_as_uint(rmv));
    }
#pragma unroll
    for (int j = 0; j < 4; j++) {
        atomicMin(&cmin_s[2 * tx + 32 * j],     __float_as_uint(cminv[2 * j]));
        atomicMin(&cmin_s[2 * tx + 32 * j + 1], __float_as_uint(cminv[2 * j + 1]));
    }
    __syncthreads();

    if (t < TILE) atomicMin(&g_rowmin[b * NPTS + brow + t], rmin_s[t]);
    else          atomicMin(&g_colmin[b * MPTS + bcol + (t - TILE)], cmin_s[t - TILE]);
}

// ---------------------------------------------------------------------------
// Kernel 3: deterministic weighted-sum reduction -> scalar
// ---------------------------------------------------------------------------
__global__ void finish_kernel(const float* __restrict__ w1,
                              const float* __restrict__ w2,
                              float* __restrict__ out) {
    __shared__ float red[256];
    int t = threadIdx.x;
    float s = 0.0f;
    for (int i = t; i < BATCH * NPTS; i += 256)
        s += w1[i] * __uint_as_float(g_rowmin[i]);
    for (int i = t; i < BATCH * MPTS; i += 256)
        s += w2[i] * __uint_as_float(g_colmin[i]);
    red[t] = s;
    __syncthreads();
    for (int o = 128; o > 0; o >>= 1) {
        if (t < o) red[t] += red[t + o];
        __syncthreads();
    }
    if (t == 0) out[0] = red[0] * 0.5f;
}

// ---------------------------------------------------------------------------
extern "C" void kernel_launch(void* const* d_in, const int* in_sizes, int n_in,
                              void* d_out, int out_size) {
    const float* set1 = (const float*)d_in[0];
    const float* set2 = (const float*)d_in[1];
    const float* w1   = (const float*)d_in[2];
    const float* w2   = (const float*)d_in[3];
    float* out = (float*)d_out;

    (void)in_sizes; (void)n_in; (void)out_size;

    int prep_threads = 2 * BATCH * NPTS;
    prep_kernel<<<(prep_threads + 255) / 256, 256>>>(set1, set2);

    dim3 grid(MPTS / TILE, NPTS / TILE, BATCH);
    chamfer_main<<<grid, 256>>>(set1, set2);

    finish_kernel<<<1, 256>>>(w1, w2, out);
}

// round 4
// speedup vs baseline: 3.6732x; 3.6732x over previous
#include <cuda_runtime.h>
#include <cuda_bf16.h>
#include <cstdint>

#define BATCH 8
#define NPTS  4096
#define MPTS  4096
#define CDIM  128
#define TILE  128
#define INF_BITS 0x7F800000u

// ---------------- device scratch (no allocation allowed) -------------------
__device__ unsigned       g_rowmin[BATCH * NPTS];
__device__ unsigned       g_colmin[BATCH * MPTS];
__device__ float          g_norm1[BATCH * NPTS];
__device__ float          g_norm2[BATCH * MPTS];
__device__ __nv_bfloat16  g_bf1[BATCH * NPTS * CDIM];   // 8.4 MB
__device__ __nv_bfloat16  g_bf2[BATCH * MPTS * CDIM];   // 8.4 MB

// ---------------- PTX helpers (plain sm_80+ instructions only) -------------
__device__ __forceinline__ uint32_t smem_u32(const void* p) {
    uint32_t a;
    asm("{ .reg .u64 t; cvta.to.shared.u64 t, %1; cvt.u32.u64 %0, t; }" : "=r"(a) : "l"(p));
    return a;
}
__device__ __forceinline__ void ldmatrix_x4(uint32_t& r0, uint32_t& r1,
                                            uint32_t& r2, uint32_t& r3, uint32_t addr) {
    asm volatile("ldmatrix.sync.aligned.m8n8.x4.shared.b16 {%0,%1,%2,%3}, [%4];"
                 : "=r"(r0), "=r"(r1), "=r"(r2), "=r"(r3) : "r"(addr));
}
__device__ __forceinline__ void mma16816(float* d, const uint32_t* a,
                                         uint32_t b0, uint32_t b1) {
    asm volatile("mma.sync.aligned.m16n8k16.row.col.f32.bf16.bf16.f32 "
                 "{%0,%1,%2,%3}, {%4,%5,%6,%7}, {%8,%9}, {%0,%1,%2,%3};"
                 : "+f"(d[0]), "+f"(d[1]), "+f"(d[2]), "+f"(d[3])
                 : "r"(a[0]), "r"(a[1]), "r"(a[2]), "r"(a[3]), "r"(b0), "r"(b1));
}

// ---------------- kernel 1: fp32 -> bf16 convert (both sets) ----------------
__global__ void convert_kernel(const float* __restrict__ s1, const float* __restrict__ s2) {
    const int per_set = BATCH * NPTS * CDIM;
    int idx = blockIdx.x * blockDim.x + threadIdx.x;
    size_t e = (size_t)idx * 8;
    const float* src;
    __nv_bfloat16* dst;
    if (e < (size_t)per_set) { src = s1; dst = g_bf1; }
    else { src = s2; dst = g_bf2; e -= per_set; }
    float4 a = *reinterpret_cast<const float4*>(src + e);
    float4 b = *reinterpret_cast<const float4*>(src + e + 4);
    __nv_bfloat162 p0 = __floats2bfloat162_rn(a.x, a.y);
    __nv_bfloat162 p1 = __floats2bfloat162_rn(a.z, a.w);
    __nv_bfloat162 p2 = __floats2bfloat162_rn(b.x, b.y);
    __nv_bfloat162 p3 = __floats2bfloat162_rn(b.z, b.w);
    uint4 o;
    o.x = *reinterpret_cast<unsigned*>(&p0);
    o.y = *reinterpret_cast<unsigned*>(&p1);
    o.z = *reinterpret_cast<unsigned*>(&p2);
    o.w = *reinterpret_cast<unsigned*>(&p3);
    *reinterpret_cast<uint4*>(dst + e) = o;
}

// ---------------- kernel 2: norms from bf16 + init mins ---------------------
__global__ void norm_kernel() {
    int idx = blockIdx.x * blockDim.x + threadIdx.x;
    const int total1 = BATCH * NPTS;
    const __nv_bfloat16* src;
    int j;
    if (idx < total1) { src = g_bf1; j = idx; }
    else { src = g_bf2; j = idx - total1; }
    const uint4* p = reinterpret_cast<const uint4*>(src + (size_t)j * CDIM);
    float s = 0.f;
#pragma unroll
    for (int i = 0; i < CDIM / 8; i++) {
        uint4 v = p[i];
        unsigned w[4] = {v.x, v.y, v.z, v.w};
#pragma unroll
        for (int q = 0; q < 4; q++) {
            float2 f = __bfloat1622float2(*reinterpret_cast<__nv_bfloat162*>(&w[q]));
            s += f.x * f.x + f.y * f.y;
        }
    }
    if (idx < total1) { g_norm1[j] = s; g_rowmin[j] = INF_BITS; }
    else              { g_norm2[j] = s; g_colmin[j] = INF_BITS; }
}

// ---------------- kernel 3: mma.sync GEMM tile + min epilogue ----------------
// smem: A 0..32K, B 32K..64K, n1 @65536, n2 @66048, rmin @66560, cmin @67072
static constexpr int SMEM_B_OFF  = 32768;
static constexpr int SMEM_N1     = 65536;
static constexpr int SMEM_N2     = 66048;
static constexpr int SMEM_RMIN   = 66560;
static constexpr int SMEM_CMIN   = 67072;
static constexpr int SMEM_TOTAL  = 67584;

__global__ __launch_bounds__(256, 2)
void chamfer_mma() {
    extern __shared__ char smem[];
    const uint32_t sb = smem_u32(smem);
    const int tid  = threadIdx.x;
    const int wid  = tid >> 5;
    const int lane = tid & 31;
    const int wr   = wid >> 2;   // warp row 0..1 (64 rows each)
    const int wc   = wid & 3;    // warp col 0..3 (32 cols each)
    const int bcol = blockIdx.x * TILE;
    const int brow = blockIdx.y * TILE;
    const int b    = blockIdx.z;

    float*    n1s    = reinterpret_cast<float*>(smem + SMEM_N1);
    float*    n2s    = reinterpret_cast<float*>(smem + SMEM_N2);
    unsigned* rmin_s = reinterpret_cast<unsigned*>(smem + SMEM_RMIN);
    unsigned* cmin_s = reinterpret_cast<unsigned*>(smem + SMEM_CMIN);

    // ---- load 128x128 bf16 tiles, K-major, xor-swizzled 16B chunks ----
    const __nv_bfloat16* Ag = g_bf1 + ((size_t)b * NPTS + brow) * CDIM;
    const __nv_bfloat16* Bg = g_bf2 + ((size_t)b * MPTS + bcol) * CDIM;
#pragma unroll
    for (int it = 0; it < 8; it++) {
        int c = it * 256 + tid;            // 2048 chunks of 16B
        int row = c >> 4, col16 = c & 15;
        int so = row * 256 + ((col16 ^ (row & 7)) << 4);
        *reinterpret_cast<uint4*>(smem + so) =
            *reinterpret_cast<const uint4*>(Ag + row * CDIM + col16 * 8);
        *reinterpret_cast<uint4*>(smem + SMEM_B_OFF + so) =
            *reinterpret_cast<const uint4*>(Bg + row * CDIM + col16 * 8);
    }
    if (tid < TILE) {
        n1s[tid] = g_norm1[b * NPTS + brow + tid];
        n2s[tid] = g_norm2[b * MPTS + bcol + tid];
        rmin_s[tid] = INF_BITS;
        cmin_s[tid] = INF_BITS;
    }
    __syncthreads();

    // ---- mainloop: 8 k-steps of 16, 16 mma each ----
    float acc[4][4][4] = {};
    const int m  = lane >> 3;    // ldmatrix sub-matrix id 0..3
    const int li = lane & 7;     // row within 8-row group; also (r&7) since bases are 8-aligned
    const int ksel = m >> 1;     // which half of the 16-k step

    uint32_t a_base[4], b_base[2];
#pragma unroll
    for (int mi = 0; mi < 4; mi++)
        a_base[mi] = sb + (wr * 64 + mi * 16 + (m & 1) * 8 + li) * 256;
#pragma unroll
    for (int nj2 = 0; nj2 < 2; nj2++)
        b_base[nj2] = sb + SMEM_B_OFF + (wc * 32 + nj2 * 16 + (m & 1) * 8 + li) * 256;

#pragma unroll
    for (int kk = 0; kk < 8; kk++) {
        const uint32_t xoff = (uint32_t)(((kk * 2 + ksel) ^ li) << 4);
        uint32_t af[4][4], bf[2][4];
#pragma unroll
        for (int mi = 0; mi < 4; mi++)
            ldmatrix_x4(af[mi][0], af[mi][1], af[mi][2], af[mi][3], a_base[mi] + xoff);
#pragma unroll
        for (int nj2 = 0; nj2 < 2; nj2++)
            ldmatrix_x4(bf[nj2][0], bf[nj2][1], bf[nj2][2], bf[nj2][3], b_base[nj2] + xoff);
#pragma unroll
        for (int mi = 0; mi < 4; mi++)
#pragma unroll
            for (int nj = 0; nj < 4; nj++)
                mma16816(acc[mi][nj], af[mi], bf[nj >> 1][nj & 1], bf[nj >> 1][2 + (nj & 1)]);
    }

    // ---- epilogue: d^2 = max(n1+n2-2dot, 0); fold row/col mins ----
    const float INF = __uint_as_float(INF_BITS);
    const int q = lane >> 2;     // accumulator row within atom
    const int s = lane & 3;      // accumulator col-pair within atom

    float n2c[4][2], n1r[4][2];
#pragma unroll
    for (int nj = 0; nj < 4; nj++) {
        n2c[nj][0] = n2s[wc * 32 + nj * 8 + 2 * s];
        n2c[nj][1] = n2s[wc * 32 + nj * 8 + 2 * s + 1];
    }
#pragma unroll
    for (int mi = 0; mi < 4; mi++) {
        n1r[mi][0] = n1s[wr * 64 + mi * 16 + q];
        n1r[mi][1] = n1s[wr * 64 + mi * 16 + q + 8];
    }

    float colm[4][2];
#pragma unroll
    for (int nj = 0; nj < 4; nj++) { colm[nj][0] = INF; colm[nj][1] = INF; }

#pragma unroll
    for (int mi = 0; mi < 4; mi++) {
        float r0 = INF, r1 = INF;
#pragma unroll
        for (int nj = 0; nj < 4; nj++) {
            float d2a = fmaxf(n1r[mi][0] + n2c[nj][0] - 2.0f * acc[mi][nj][0], 0.0f);
            float d2b = fmaxf(n1r[mi][0] + n2c[nj][1] - 2.0f * acc[mi][nj][1], 0.0f);
            float d2c = fmaxf(n1r[mi][1] + n2c[nj][0] - 2.0f * acc[mi][nj][2], 0.0f);
            float d2d = fmaxf(n1r[mi][1] + n2c[nj][1] - 2.0f * acc[mi][nj][3], 0.0f);
            r0 = fminf(r0, fminf(d2a, d2b));
            r1 = fminf(r1, fminf(d2c, d2d));
            colm[nj][0] = fminf(colm[nj][0], fminf(d2a, d2c));
            colm[nj][1] = fminf(colm[nj][1], fminf(d2b, d2d));
        }
        // reduce over the 4 lanes sharing this row (same q, varying s)
        r0 = fminf(r0, __shfl_xor_sync(0xffffffffu, r0, 1));
        r0 = fminf(r0, __shfl_xor_sync(0xffffffffu, r0, 2));
        r1 = fminf(r1, __shfl_xor_sync(0xffffffffu, r1, 1));
        r1 = fminf(r1, __shfl_xor_sync(0xffffffffu, r1, 2));
        if (s == 0) {
            atomicMin(&rmin_s[wr * 64 + mi * 16 + q],     __float_as_uint(r0));
            atomicMin(&rmin_s[wr * 64 + mi * 16 + q + 8], __float_as_uint(r1));
        }
    }
#pragma unroll
    for (int nj = 0; nj < 4; nj++) {
#pragma unroll
        for (int h = 0; h < 2; h++) {
            float v = colm[nj][h];
            v = fminf(v, __shfl_xor_sync(0xffffffffu, v, 4));
            v = fminf(v, __shfl_xor_sync(0xffffffffu, v, 8));
            v = fminf(v, __shfl_xor_sync(0xffffffffu, v, 16));
            if (q == 0)
                atomicMin(&cmin_s[wc * 32 + nj * 8 + 2 * s + h], __float_as_uint(v));
        }
    }
    __syncthreads();

    if (tid < TILE) {
        atomicMin(&g_rowmin[b * NPTS + brow + tid], rmin_s[tid]);
        atomicMin(&g_colmin[b * MPTS + bcol + tid], cmin_s[tid]);
    }
}

// ---------------- kernel 4: weighted sum (mins hold d^2 -> sqrt here) -------
__global__ void finish_kernel(const float* __restrict__ w1,
                              const float* __restrict__ w2,
                              float* __restrict__ out) {
    __shared__ float red[256];
    int t = threadIdx.x;
    float s = 0.0f;
    for (int i = t; i < BATCH * NPTS; i += 256)
        s += w1[i] * sqrtf(__uint_as_float(g_rowmin[i]));
    for (int i = t; i < BATCH * MPTS; i += 256)
        s += w2[i] * sqrtf(__uint_as_float(g_colmin[i]));
    red[t] = s;
    __syncthreads();
    for (int o = 128; o > 0; o >>= 1) {
        if (t < o) red[t] += red[t + o];
        __syncthreads();
    }
    if (t == 0) out[0] = red[0] * 0.5f;
}

// ---------------------------------------------------------------------------
extern "C" void kernel_launch(void* const* d_in, const int* in_sizes, int n_in,
                              void* d_out, int out_size) {
    const float* set1 = (const float*)d_in[0];
    const float* set2 = (const float*)d_in[1];
    const float* w1   = (const float*)d_in[2];
    const float* w2   = (const float*)d_in[3];
    float* out = (float*)d_out;
    (void)in_sizes; (void)n_in; (void)out_size;

    static bool attr_done = false;
    if (!attr_done) {
        cudaFuncSetAttribute(chamfer_mma, cudaFuncAttributeMaxDynamicSharedMemorySize, SMEM_TOTAL);
        attr_done = true;
    }

    convert_kernel<<<(2 * BATCH * NPTS * CDIM / 8 + 255) / 256, 256>>>(set1, set2);
    norm_kernel<<<(2 * BATCH * NPTS + 255) / 256, 256>>>();
    dim3 grid(MPTS / TILE, NPTS / TILE, BATCH);
    chamfer_mma<<<grid, 256, SMEM_TOTAL>>>();
    finish_kernel<<<1, 256>>>(w1, w2, out);
}

// round 6
// speedup vs baseline: 5.3915x; 1.4678x over previous
#include <cuda_runtime.h>
#include <cuda_bf16.h>
#include <cstdint>

#define BATCH 8
#define NPTS  4096
#define MPTS  4096
#define CDIM  128
#define TILE  128
#define INF_BITS 0x7F800000u

// ---------------- device scratch (no allocation allowed) -------------------
__device__ unsigned       g_rowmin[BATCH * NPTS];
__device__ unsigned       g_colmin[BATCH * MPTS];
__device__ float          g_norm1[BATCH * NPTS];
__device__ float          g_norm2[BATCH * MPTS];
__device__ __nv_bfloat16  g_bf1[BATCH * NPTS * CDIM];   // 8.4 MB
__device__ __nv_bfloat16  g_bf2[BATCH * MPTS * CDIM];   // 8.4 MB
__device__ float          g_partial[64];

// ---------------- PTX helpers (plain sm_80+ instructions only) -------------
__device__ __forceinline__ uint32_t smem_u32(const void* p) {
    uint32_t a;
    asm("{ .reg .u64 t; cvta.to.shared.u64 t, %1; cvt.u32.u64 %0, t; }" : "=r"(a) : "l"(p));
    return a;
}
__device__ __forceinline__ void ldmatrix_x4(uint32_t& r0, uint32_t& r1,
                                            uint32_t& r2, uint32_t& r3, uint32_t addr) {
    asm volatile("ldmatrix.sync.aligned.m8n8.x4.shared.b16 {%0,%1,%2,%3}, [%4];"
                 : "=r"(r0), "=r"(r1), "=r"(r2), "=r"(r3) : "r"(addr));
}
__device__ __forceinline__ void mma16816(float* d, const uint32_t* a,
                                         uint32_t b0, uint32_t b1) {
    asm volatile("mma.sync.aligned.m16n8k16.row.col.f32.bf16.bf16.f32 "
                 "{%0,%1,%2,%3}, {%4,%5,%6,%7}, {%8,%9}, {%0,%1,%2,%3};"
                 : "+f"(d[0]), "+f"(d[1]), "+f"(d[2]), "+f"(d[3])
                 : "r"(a[0]), "r"(a[1]), "r"(a[2]), "r"(a[3]), "r"(b0), "r"(b1));
}

// ---------------- kernel 1: fused fp32->bf16 convert + norm + min-init ------
// 8 threads per row; each thread handles 16 contiguous elements.
__global__ void prep_kernel(const float* __restrict__ s1, const float* __restrict__ s2) {
    const int total1 = BATCH * NPTS;
    int row = blockIdx.x * 32 + (threadIdx.x >> 3);   // 32 rows per block
    int sub = threadIdx.x & 7;
    const float* src;
    __nv_bfloat16* dst;
    int j;
    if (row < total1) { src = s1; dst = g_bf1; j = row; }
    else { src = s2; dst = g_bf2; j = row - total1; }
    const float* rp = src + (size_t)j * CDIM + sub * 16;
    __nv_bfloat16* wp = dst + (size_t)j * CDIM + sub * 16;

    float s = 0.f;
#pragma unroll
    for (int h = 0; h < 2; h++) {
        float4 a = *reinterpret_cast<const float4*>(rp + h * 8);
        float4 b = *reinterpret_cast<const float4*>(rp + h * 8 + 4);
        __nv_bfloat162 p0 = __floats2bfloat162_rn(a.x, a.y);
        __nv_bfloat162 p1 = __floats2bfloat162_rn(a.z, a.w);
        __nv_bfloat162 p2 = __floats2bfloat162_rn(b.x, b.y);
        __nv_bfloat162 p3 = __floats2bfloat162_rn(b.z, b.w);
        uint4 o;
        o.x = *reinterpret_cast<unsigned*>(&p0);
        o.y = *reinterpret_cast<unsigned*>(&p1);
        o.z = *reinterpret_cast<unsigned*>(&p2);
        o.w = *reinterpret_cast<unsigned*>(&p3);
        *reinterpret_cast<uint4*>(wp + h * 8) = o;
        // norm from the ROUNDED values (keeps d^2 = ||x̂-ŷ||^2 exact in bf16 space)
        float2 f0 = __bfloat1622float2(p0);
        float2 f1 = __bfloat1622float2(p1);
        float2 f2 = __bfloat1622float2(p2);
        float2 f3 = __bfloat1622float2(p3);
        s += f0.x * f0.x + f0.y * f0.y + f1.x * f1.x + f1.y * f1.y;
        s += f2.x * f2.x + f2.y * f2.y + f3.x * f3.x + f3.y * f3.y;
    }
    // reduce over the 8 lanes of this row (width-8 shfl)
    s += __shfl_down_sync(0xffffffffu, s, 4, 8);
    s += __shfl_down_sync(0xffffffffu, s, 2, 8);
    s += __shfl_down_sync(0xffffffffu, s, 1, 8);
    if (sub == 0) {
        if (row < total1) { g_norm1[j] = s; g_rowmin[j] = INF_BITS; }
        else              { g_norm2[j] = s; g_colmin[j] = INF_BITS; }
    }
}

// ---------------- kernel 2: mma.sync GEMM tile + min epilogue ----------------
static constexpr int SMEM_B_OFF  = 32768;
static constexpr int SMEM_N1     = 65536;
static constexpr int SMEM_N2     = 66048;
static constexpr int SMEM_RMIN   = 66560;
static constexpr int SMEM_CMIN   = 67072;
static constexpr int SMEM_TOTAL  = 67584;

__global__ __launch_bounds__(256, 2)
void chamfer_mma() {
    extern __shared__ char smem[];
    const uint32_t sb = smem_u32(smem);
    const int tid  = threadIdx.x;
    const int wid  = tid >> 5;
    const int lane = tid & 31;
    const int wr   = wid >> 2;
    const int wc   = wid & 3;
    const int bcol = blockIdx.x * TILE;
    const int brow = blockIdx.y * TILE;
    const int b    = blockIdx.z;

    float*    n1s    = reinterpret_cast<float*>(smem + SMEM_N1);
    float*    n2s    = reinterpret_cast<float*>(smem + SMEM_N2);
    unsigned* rmin_s = reinterpret_cast<unsigned*>(smem + SMEM_RMIN);
    unsigned* cmin_s = reinterpret_cast<unsigned*>(smem + SMEM_CMIN);

    const __nv_bfloat16* Ag = g_bf1 + ((size_t)b * NPTS + brow) * CDIM;
    const __nv_bfloat16* Bg = g_bf2 + ((size_t)b * MPTS + bcol) * CDIM;
#pragma unroll
    for (int it = 0; it < 8; it++) {
        int c = it * 256 + tid;
        int row = c >> 4, col16 = c & 15;
        int so = row * 256 + ((col16 ^ (row & 7)) << 4);
        *reinterpret_cast<uint4*>(smem + so) =
            *reinterpret_cast<const uint4*>(Ag + row * CDIM + col16 * 8);
        *reinterpret_cast<uint4*>(smem + SMEM_B_OFF + so) =
            *reinterpret_cast<const uint4*>(Bg + row * CDIM + col16 * 8);
    }
    if (tid < TILE) {
        n1s[tid] = g_norm1[b * NPTS + brow + tid];
        n2s[tid] = g_norm2[b * MPTS + bcol + tid];
        rmin_s[tid] = INF_BITS;
        cmin_s[tid] = INF_BITS;
    }
    __syncthreads();

    float acc[4][4][4] = {};
    const int m  = lane >> 3;
    const int li = lane & 7;
    const int ksel = m >> 1;

    uint32_t a_base[4], b_base[2];
#pragma unroll
    for (int mi = 0; mi < 4; mi++)
        a_base[mi] = sb + (wr * 64 + mi * 16 + (m & 1) * 8 + li) * 256;
#pragma unroll
    for (int nj2 = 0; nj2 < 2; nj2++)
        b_base[nj2] = sb + SMEM_B_OFF + (wc * 32 + nj2 * 16 + (m & 1) * 8 + li) * 256;

#pragma unroll
    for (int kk = 0; kk < 8; kk++) {
        const uint32_t xoff = (uint32_t)(((kk * 2 + ksel) ^ li) << 4);
        uint32_t af[4][4], bf[2][4];
#pragma unroll
        for (int mi = 0; mi < 4; mi++)
            ldmatrix_x4(af[mi][0], af[mi][1], af[mi][2], af[mi][3], a_base[mi] + xoff);
#pragma unroll
        for (int nj2 = 0; nj2 < 2; nj2++)
            ldmatrix_x4(bf[nj2][0], bf[nj2][1], bf[nj2][2], bf[nj2][3], b_base[nj2] + xoff);
#pragma unroll
        for (int mi = 0; mi < 4; mi++)
#pragma unroll
            for (int nj = 0; nj < 4; nj++)
                mma16816(acc[mi][nj], af[mi], bf[nj >> 1][nj & 1], bf[nj >> 1][2 + (nj & 1)]);
    }

    const float INF = __uint_as_float(INF_BITS);
    const int q = lane >> 2;
    const int s = lane & 3;

    float n2c[4][2], n1r[4][2];
#pragma unroll
    for (int nj = 0; nj < 4; nj++) {
        n2c[nj][0] = n2s[wc * 32 + nj * 8 + 2 * s];
        n2c[nj][1] = n2s[wc * 32 + nj * 8 + 2 * s + 1];
    }
#pragma unroll
    for (int mi = 0; mi < 4; mi++) {
        n1r[mi][0] = n1s[wr * 64 + mi * 16 + q];
        n1r[mi][1] = n1s[wr * 64 + mi * 16 + q + 8];
    }

    float colm[4][2];
#pragma unroll
    for (int nj = 0; nj < 4; nj++) { colm[nj][0] = INF; colm[nj][1] = INF; }

#pragma unroll
    for (int mi = 0; mi < 4; mi++) {
        float r0 = INF, r1 = INF;
#pragma unroll
        for (int nj = 0; nj < 4; nj++) {
            float d2a = fmaxf(n1r[mi][0] + n2c[nj][0] - 2.0f * acc[mi][nj][0], 0.0f);
            float d2b = fmaxf(n1r[mi][0] + n2c[nj][1] - 2.0f * acc[mi][nj][1], 0.0f);
            float d2c = fmaxf(n1r[mi][1] + n2c[nj][0] - 2.0f * acc[mi][nj][2], 0.0f);
            float d2d = fmaxf(n1r[mi][1] + n2c[nj][1] - 2.0f * acc[mi][nj][3], 0.0f);
            r0 = fminf(r0, fminf(d2a, d2b));
            r1 = fminf(r1, fminf(d2c, d2d));
            colm[nj][0] = fminf(colm[nj][0], fminf(d2a, d2c));
            colm[nj][1] = fminf(colm[nj][1], fminf(d2b, d2d));
        }
        r0 = fminf(r0, __shfl_xor_sync(0xffffffffu, r0, 1));
        r0 = fminf(r0, __shfl_xor_sync(0xffffffffu, r0, 2));
        r1 = fminf(r1, __shfl_xor_sync(0xffffffffu, r1, 1));
        r1 = fminf(r1, __shfl_xor_sync(0xffffffffu, r1, 2));
        if (s == 0) {
            atomicMin(&rmin_s[wr * 64 + mi * 16 + q],     __float_as_uint(r0));
            atomicMin(&rmin_s[wr * 64 + mi * 16 + q + 8], __float_as_uint(r1));
        }
    }
#pragma unroll
    for (int nj = 0; nj < 4; nj++) {
#pragma unroll
        for (int h = 0; h < 2; h++) {
            float v = colm[nj][h];
            v = fminf(v, __shfl_xor_sync(0xffffffffu, v, 4));
            v = fminf(v, __shfl_xor_sync(0xffffffffu, v, 8));
            v = fminf(v, __shfl_xor_sync(0xffffffffu, v, 16));
            if (q == 0)
                atomicMin(&cmin_s[wc * 32 + nj * 8 + 2 * s + h], __float_as_uint(v));
        }
    }
    __syncthreads();

    if (tid < TILE) {
        atomicMin(&g_rowmin[b * NPTS + brow + tid], rmin_s[tid]);
        atomicMin(&g_colmin[b * MPTS + bcol + tid], cmin_s[tid]);
    }
}

// ---------------- kernel 3a: parallel partial reduction (deterministic) -----
// 64 blocks x 1024 elements = 65536 = 2 * 32768 (rowmin then colmin). In-bounds.
__global__ void reduce_stage1(const float* __restrict__ w1,
                              const float* __restrict__ w2) {
    __shared__ float red[256];
    const int t = threadIdx.x;
    const int bid = blockIdx.x;            // 0..63
    const int total1 = BATCH * NPTS;       // 32768
    float s = 0.0f;
#pragma unroll
    for (int k = 0; k < 4; k++) {
        int idx = bid * 1024 + k * 256 + t; // 0 .. 65535
        if (idx < total1) {
            s += w1[idx] * sqrtf(__uint_as_float(g_rowmin[idx]));
        } else {
            int j = idx - total1;           // 0 .. 32767
            s += w2[j] * sqrtf(__uint_as_float(g_colmin[j]));
        }
    }
    red[t] = s;
    __syncthreads();
    for (int o = 128; o > 0; o >>= 1) {
        if (t < o) red[t] += red[t + o];
        __syncthreads();
    }
    if (t == 0) g_partial[bid] = red[0];
}

// ---------------- kernel 3b: final sum ---------------------------------------
__global__ void reduce_stage2(float* __restrict__ out) {
    __shared__ float red[64];
    int t = threadIdx.x;                   // 64 threads
    red[t] = g_partial[t];
    __syncthreads();
    for (int o = 32; o > 0; o >>= 1) {
        if (t < o) red[t] += red[t + o];
        __syncthreads();
    }
    if (t == 0) out[0] = red[0] * 0.5f;
}

// ---------------------------------------------------------------------------
extern "C" void kernel_launch(void* const* d_in, const int* in_sizes, int n_in,
                              void* d_out, int out_size) {
    const float* set1 = (const float*)d_in[0];
    const float* set2 = (const float*)d_in[1];
    const float* w1   = (const float*)d_in[2];
    const float* w2   = (const float*)d_in[3];
    float* out = (float*)d_out;
    (void)in_sizes; (void)n_in; (void)out_size;

    static bool attr_done = false;
    if (!attr_done) {
        cudaFuncSetAttribute(chamfer_mma, cudaFuncAttributeMaxDynamicSharedMemorySize, SMEM_TOTAL);
        attr_done = true;
    }

    // 1) fused convert + norms + min-init: 65536 rows, 32 rows/block
    prep_kernel<<<2 * BATCH * NPTS / 32, 256>>>(set1, set2);
    // 2) main GEMM + mins
    dim3 grid(MPTS / TILE, NPTS / TILE, BATCH);
    chamfer_mma<<<grid, 256, SMEM_TOTAL>>>();
    // 3) deterministic two-stage weighted reduction (65536 elements total)
    reduce_stage1<<<64, 256>>>(w1, w2);
    reduce_stage2<<<1, 64>>>(out);
}